// round 14
// baseline (speedup 1.0000x reference)
#include <cuda_runtime.h>
#include <cuda_fp16.h>
#include <stdint.h>

#define TT 256
#define BB 128
#define VV 256
#define EE 512
#define NH 1024
#define TB (TT*BB)          // 32768
#define G4 (4*NH)           // 4096

// ---------------- static device scratch ----------------
__device__ __align__(16) __half g_inph[(size_t)TB*VV];
__device__ __align__(16) __half g_embs[(size_t)TB*EE];
__device__ __align__(16) float  g_X[(size_t)TB*G4];
__device__ __align__(16) __half g_H0[(size_t)TB*NH];
__device__ __align__(16) __half g_H1[(size_t)TB*NH];
__device__ __align__(16) __half g_embT[EE*VV];           // [512][256]
__device__ __align__(16) __half g_w0xT[(size_t)G4*EE];   // [4096][512]
__device__ __align__(16) __half g_w0hT[(size_t)G4*NH];   // [4096][1024]
__device__ __align__(16) __half g_w1xT[(size_t)G4*NH];   // [4096][1024]
__device__ __align__(16) __half g_w1hT[(size_t)G4*NH];   // [4096][1024]
__device__ __align__(16) __half g_owT[VV*NH];            // [256][1024]
__device__ int g_ctr[2];

// ---------------- helpers ----------------
__device__ __forceinline__ void mma16(float d[4], const unsigned a[4], const unsigned b[2]) {
    asm volatile(
        "mma.sync.aligned.m16n8k16.row.col.f32.f16.f16.f32 "
        "{%0,%1,%2,%3}, {%4,%5,%6,%7}, {%8,%9}, {%0,%1,%2,%3};\n"
        : "+f"(d[0]), "+f"(d[1]), "+f"(d[2]), "+f"(d[3])
        : "r"(a[0]), "r"(a[1]), "r"(a[2]), "r"(a[3]), "r"(b[0]), "r"(b[1]));
}
__device__ __forceinline__ void ldsm_x4(unsigned r[4], const __half* p) {
    unsigned a = (unsigned)__cvta_generic_to_shared(p);
    asm volatile("ldmatrix.sync.aligned.m8n8.x4.shared.b16 {%0,%1,%2,%3}, [%4];\n"
        : "=r"(r[0]), "=r"(r[1]), "=r"(r[2]), "=r"(r[3]) : "r"(a));
}
__device__ __forceinline__ void cpa16(__half* dst, const __half* src) {
    unsigned d = (unsigned)__cvta_generic_to_shared(dst);
    asm volatile("cp.async.cg.shared.global [%0], [%1], 16;\n" :: "r"(d), "l"(src));
}
#define CPA_COMMIT() asm volatile("cp.async.commit_group;\n" ::: "memory")
template <int N> __device__ __forceinline__ void cpa_wait() {
    asm volatile("cp.async.wait_group %0;\n" :: "n"(N) : "memory");
}
__device__ __forceinline__ void cstore2(float* C, size_t i, float a, float b) {
    *(float2*)&C[i] = make_float2(a, b);
}
__device__ __forceinline__ void cstore2(__half* C, size_t i, float a, float b) {
    *(__half2*)&C[i] = __floats2half2_rn(a, b);
}
__device__ __forceinline__ float sigf(float x) { return 1.f / (1.f + __expf(-x)); }

__global__ void zero_i(int* p) { if (threadIdx.x < 2) p[threadIdx.x] = 0; }
__global__ void f2h_kernel(const float* __restrict__ s, __half* __restrict__ d, int n) {
    for (int i = blockIdx.x * blockDim.x + threadIdx.x; i < n; i += gridDim.x * blockDim.x)
        d[i] = __float2half(s[i]);
}
// src fp32 [K][N] (row stride lds) -> dst fp16 [N][K]
__global__ void transpose_cvt(const float* __restrict__ src, int lds,
                              __half* __restrict__ dst, int K, int N) {
    __shared__ float tile[32][33];
    int kb = blockIdx.x * 32, nb = blockIdx.y * 32;
    #pragma unroll
    for (int i = threadIdx.y; i < 32; i += 8) {
        int k = kb + i, n = nb + threadIdx.x;
        tile[i][threadIdx.x] = (k < K && n < N) ? src[(size_t)k * lds + n] : 0.f;
    }
    __syncthreads();
    #pragma unroll
    for (int i = threadIdx.y; i < 32; i += 8) {
        int n = nb + i, k = kb + threadIdx.x;
        if (n < N && k < K) dst[(size_t)n * K + k] = __float2half(tile[threadIdx.x][i]);
    }
}

// ---------------- fp16 GEMM (validated R7): C = A @ Bt^T (+bias), 128x128 tile ----------------
#define GAST (128*40)
#define GBST (128*40)
#define GEMM_SMEM ((4*(GAST+GBST))*2)

template <typename TOUT>
__global__ void __launch_bounds__(256, 2) gemm16(
    const __half* __restrict__ A, int lda,
    const __half* __restrict__ Bt,
    TOUT* __restrict__ C, int ldc,
    const float* __restrict__ bias,
    int M, int N, int K)
{
    extern __shared__ __half sm[];
    __half* As = sm;
    __half* Bs = sm + 4*GAST;

    const int tid = threadIdx.x;
    const int bm = blockIdx.y * 128, bn = blockIdx.x * 128;
    const int wid = tid >> 5, lane = tid & 31;
    const int wr = (wid & 1) * 64, wc = (wid >> 1) * 32;
    const int r = lane >> 2, cl = lane & 3;

    float acc[4][4][4];
    #pragma unroll
    for (int i = 0; i < 4; ++i)
        #pragma unroll
        for (int j = 0; j < 4; ++j)
            #pragma unroll
            for (int k = 0; k < 4; ++k) acc[i][j][k] = 0.f;

    auto loadG = [&](int s, int kt) {
        #pragma unroll
        for (int i = 0; i < 2; ++i) {
            int idx = tid + i * 256;
            int row = idx >> 2, cc = idx & 3;
            cpa16(As + s*GAST + row*40 + cc*8,
                  A + (size_t)(bm + row) * lda + kt*32 + cc*8);
            cpa16(Bs + s*GBST + row*40 + cc*8,
                  Bt + (size_t)(bn + row) * K + kt*32 + cc*8);
        }
    };

    const int ktiles = K >> 5;
    #pragma unroll
    for (int s = 0; s < 3; ++s) { if (s < ktiles) loadG(s, s); CPA_COMMIT(); }

    const int a_row = (lane & 15);
    const int a_col = (lane >> 4) << 3;
    const int b_row = (lane & 7) + ((lane >> 4) << 3);
    const int b_col = (lane & 8);

    for (int kt = 0; kt < ktiles; ++kt) {
        cpa_wait<2>();
        __syncthreads();
        if (kt + 3 < ktiles) loadG((kt + 3) & 3, kt + 3);
        CPA_COMMIT();

        const __half* sA = As + (kt & 3) * GAST;
        const __half* sB = Bs + (kt & 3) * GBST;
        #pragma unroll
        for (int ks = 0; ks < 2; ++ks) {
            const int k0 = ks * 16;
            unsigned af[4][4], bf01[4], bf23[4];
            #pragma unroll
            for (int mt = 0; mt < 4; ++mt)
                ldsm_x4(af[mt], sA + (wr + mt*16 + a_row)*40 + k0 + a_col);
            ldsm_x4(bf01, sB + (wc      + b_row)*40 + k0 + b_col);
            ldsm_x4(bf23, sB + (wc + 16 + b_row)*40 + k0 + b_col);
            #pragma unroll
            for (int mt = 0; mt < 4; ++mt) {
                mma16(acc[mt][0], af[mt], bf01 + 0);
                mma16(acc[mt][1], af[mt], bf01 + 2);
                mma16(acc[mt][2], af[mt], bf23 + 0);
                mma16(acc[mt][3], af[mt], bf23 + 2);
            }
        }
    }

    #pragma unroll
    for (int mt = 0; mt < 4; ++mt)
        #pragma unroll
        for (int nt = 0; nt < 4; ++nt) {
            const int row = bm + wr + mt*16 + r;
            const int col = bn + wc + nt*8 + 2*cl;
            const float b0 = bias ? bias[col]     : 0.f;
            const float b1 = bias ? bias[col + 1] : 0.f;
            cstore2(C, (size_t)row * ldc + col,       acc[mt][nt][0] + b0, acc[mt][nt][1] + b1);
            cstore2(C, (size_t)(row + 8) * ldc + col, acc[mt][nt][2] + b0, acc[mt][nt][3] + b1);
        }
}

// ---------------- persistent LSTM layer kernel ----------------
// 128 CTAs (1/SM). CTA bx owns hidden cols [bx*8, bx*8+8) of all 4 gates
// (GEMM N=32, K=1024). W_h slice (64KB) resident in smem.
// k-split warp pairs: warps w / w+4 share M-tile rows [w*32, w*32+32),
// splitting ks by parity (halves B crossbar traffic; all 8 warps stay active).
// Partial accs merged through a padded smem exchange before the epilogue.
// PUBLISH PROTOCOL: every thread waits its own cp.async groups (cpa_wait<0>)
// BEFORE the barrier that precedes cross-thread reads.
// X staged EVERY step (t=0 included) — epilogue always reads Xs.
#define BST  (32*1032)
#define AST2 (128*136)
#define XS_OFF ((BST + 3*AST2)*2)             // byte offset of X stage (fp32 [128][36])
#define ACC_OFF (XS_OFF + 128*36*4)           // byte offset of acc exchange (fp32 [8][16*36])
#define LSTM_SMEM (ACC_OFF + 8*16*36*4)

__global__ void __launch_bounds__(256, 1) lstm_layer(
    const __half* __restrict__ WhT,    // [4096][1024]
    const float*  __restrict__ X,      // [T*128][4096]
    __half* __restrict__ H,            // [T*128][1024]
    int* __restrict__ ctr)
{
    extern __shared__ __half sm[];
    __half* Bs = sm;                   // 32 x 1032 (n = gate*8+j, k = 0..1023)
    __half* As = sm + BST;             // 3 stages x 128 x 136
    float*  Xs = (float*)((char*)sm + XS_OFF);    // 128 x 36 fp32
    float*  AccS = (float*)((char*)sm + ACC_OFF); // 8 x (16 x 36) fp32

    const int tid = threadIdx.x, lane = tid & 31, wid = tid >> 5;
    const int r = lane >> 2, cl = lane & 3;
    const int bx = blockIdx.x;
    const int wid4 = wid & 3, par = wid >> 2;   // M-tile id, k-parity
    const int wr = wid4 * 32;                    // M-tile row base
    const int jj = 2 * cl;
    const int colg = bx * 8 + jj;

    // load W_h slice once: rows g*1024 + bx*8 + j  ->  Bs[g*8+j][0..1023]
    #pragma unroll
    for (int i = 0; i < 16; ++i) {
        int idx = tid + i * 256;            // 0..4095
        int n = idx >> 7, cc = idx & 127;
        int g = n >> 3, j = n & 7;
        cpa16(Bs + n*1032 + cc*8,
              WhT + (size_t)(g*1024 + bx*8 + j) * 1024 + cc*8);
    }
    CPA_COMMIT();
    cpa_wait<0>();
    __syncthreads();

    float c0 = 0.f, c1 = 0.f, c2 = 0.f, c3 = 0.f;

    // A chunk: 128 rows x 128 halfs of k (32KB), row stride 136 halfs
    auto loadA = [&](__half* dst, const __half* hsrc, int ch) {
        #pragma unroll
        for (int i = 0; i < 8; ++i) {
            int idx = tid + i * 256;        // 0..2047 (16B units)
            int row = idx >> 4, cc = idx & 15;
            cpa16(dst + row*136 + cc*8, hsrc + (size_t)row*1024 + ch*128 + cc*8);
        }
    };
    // stage this step's X gate block [128 rows][4 gates x 8 cols] into smem
    auto loadX = [&](const float* Xt) {
        #pragma unroll
        for (int i = 0; i < 4; ++i) {
            int u = tid + i * 256;          // 0..1023 (16B granules)
            int row = u >> 3, seg = u & 7;  // seg = gate*2 + half
            int g = seg >> 1, hf = seg & 1;
            cpa16((__half*)(Xs + row*36 + g*8 + hf*4),
                  (const __half*)(Xt + (size_t)row*4096 + g*1024 + bx*8 + hf*4));
        }
    };

    for (int t = 0; t < TT; ++t) {
        float acc[2][4][4];
        #pragma unroll
        for (int m = 0; m < 2; ++m)
            #pragma unroll
            for (int i = 0; i < 4; ++i)
                #pragma unroll
                for (int j = 0; j < 4; ++j) acc[m][i][j] = 0.f;

        const float* Xt = X + (size_t)t * (BB * G4);

        if (t > 0) {
            const __half* hsrc = H + (size_t)(t - 1) * BB * NH;
            loadA(As + 0*AST2, hsrc, 0); loadX(Xt); CPA_COMMIT();
            loadA(As + 1*AST2, hsrc, 1); CPA_COMMIT();

            #pragma unroll 1
            for (int kt = 0; kt < 8; ++kt) {
                cpa_wait<1>();
                __syncthreads();
                if (kt + 2 < 8) {
                    int st = kt + 2; st -= (st >= 3) ? 3 : 0; st -= (st >= 3) ? 3 : 0;
                    loadA(As + st * AST2, hsrc, kt + 2);
                }
                CPA_COMMIT();

                int sb = kt; sb -= (sb >= 3) ? 3 : 0; sb -= (sb >= 3) ? 3 : 0;
                const __half* sA = As + sb * AST2;
                // this warp handles ks of its parity: 4 of the 8 slices per round
                #pragma unroll
                for (int u = 0; u < 4; ++u) {
                    const int ksl = u * 2 + par;       // 0..7 within round
                    const int k0 = ksl * 16;
                    unsigned af[2][4];
                    #pragma unroll
                    for (int m = 0; m < 2; ++m) {
                        const int rw0 = wr + m*16 + r, rw1 = rw0 + 8;
                        af[m][0] = *(const unsigned*)&sA[rw0*136 + k0 + jj];
                        af[m][1] = *(const unsigned*)&sA[rw1*136 + k0 + jj];
                        af[m][2] = *(const unsigned*)&sA[rw0*136 + k0 + jj + 8];
                        af[m][3] = *(const unsigned*)&sA[rw1*136 + k0 + jj + 8];
                    }
                    #pragma unroll
                    for (int nt = 0; nt < 4; ++nt) {
                        const __half* bp = Bs + (size_t)(nt*8 + r)*1032 + kt*128 + k0 + jj;
                        unsigned bf[2];
                        bf[0] = *(const unsigned*)bp;
                        bf[1] = *(const unsigned*)(bp + 8);
                        mma16(acc[0][nt], af[0], bf);
                        mma16(acc[1][nt], af[1], bf);
                    }
                }
            }
        } else {
            loadX(Xt); CPA_COMMIT();   // t = 0: X must still be staged
        }

        // ---- merge partner partials: warp w keeps mt=par, gives the other ----
        const int km = par;
        const int gm = 1 - km;
        {
            float* myslot = AccS + wid * (16*36);
            #pragma unroll
            for (int nt = 0; nt < 4; ++nt) {
                const int col = nt*8 + jj;
                *(float2*)&myslot[r*36 + col]     = make_float2(acc[gm][nt][0], acc[gm][nt][1]);
                *(float2*)&myslot[(r+8)*36 + col] = make_float2(acc[gm][nt][2], acc[gm][nt][3]);
            }
        }
        cpa_wait<0>();     // publish own X cp.asyncs BEFORE the barrier
        __syncthreads();   // publishes AccS writes AND all threads' Xs stages
        {
            const float* ps = AccS + (wid ^ 4) * (16*36);
            #pragma unroll
            for (int nt = 0; nt < 4; ++nt) {
                const int col = nt*8 + jj;
                float2 v0 = *(const float2*)&ps[r*36 + col];
                float2 v1 = *(const float2*)&ps[(r+8)*36 + col];
                acc[km][nt][0] += v0.x; acc[km][nt][1] += v0.y;
                acc[km][nt][2] += v1.x; acc[km][nt][3] += v1.y;
            }
        }

        // gates + state update: warp epilogues rows [wr + km*16, +16)
        const int row0 = wr + km*16 + r, row1 = row0 + 8;
        {
            const float* xa = Xs + row0*36 + jj;
            float2 xf = *(const float2*)(xa);
            float2 xi = *(const float2*)(xa + 8);
            float2 xo = *(const float2*)(xa + 16);
            float2 xg = *(const float2*)(xa + 24);
            float f  = sigf(acc[km][0][0] + xf.x), ig  = sigf(acc[km][1][0] + xi.x);
            float o  = sigf(acc[km][2][0] + xo.x), gg  = tanhf(acc[km][3][0] + xg.x);
            c0 = f * c0 + ig * gg;
            float f1 = sigf(acc[km][0][1] + xf.y), ig1 = sigf(acc[km][1][1] + xi.y);
            float o1 = sigf(acc[km][2][1] + xo.y), gg1 = tanhf(acc[km][3][1] + xg.y);
            c1 = f1 * c1 + ig1 * gg1;
            __half2 hv = __floats2half2_rn(o * tanhf(c0), o1 * tanhf(c1));
            *(__half2*)&H[(size_t)t*BB*NH + (size_t)row0*1024 + colg] = hv;
        }
        {
            const float* xb = Xs + row1*36 + jj;
            float2 xf = *(const float2*)(xb);
            float2 xi = *(const float2*)(xb + 8);
            float2 xo = *(const float2*)(xb + 16);
            float2 xg = *(const float2*)(xb + 24);
            float f  = sigf(acc[km][0][2] + xf.x), ig  = sigf(acc[km][1][2] + xi.x);
            float o  = sigf(acc[km][2][2] + xo.x), gg  = tanhf(acc[km][3][2] + xg.x);
            c2 = f * c2 + ig * gg;
            float f1 = sigf(acc[km][0][3] + xf.y), ig1 = sigf(acc[km][1][3] + xi.y);
            float o1 = sigf(acc[km][2][3] + xo.y), gg1 = tanhf(acc[km][3][3] + xg.y);
            c3 = f1 * c3 + ig1 * gg1;
            __half2 hv = __floats2half2_rn(o * tanhf(c2), o1 * tanhf(c3));
            *(__half2*)&H[(size_t)t*BB*NH + (size_t)row1*1024 + colg] = hv;
        }

        if (t + 1 < TT) {
            __syncthreads();       // all CTA threads' H stores happen-before tid0's release
            if (tid == 0) {
                asm volatile("red.release.gpu.global.add.u32 [%0], %1;"
                             :: "l"(ctr), "r"(1) : "memory");
                const int target = 128 * (t + 1);
                int v;
                while (true) {
                    asm volatile("ld.acquire.gpu.b32 %0, [%1];" : "=r"(v) : "l"(ctr));
                    if (v >= target) break;
                    __nanosleep(64);   // backoff
                }
            }
            __syncthreads();       // broadcast acquire to whole CTA
        }
    }
}

// ---------------- launch ----------------
extern "C" void kernel_launch(void* const* d_in, const int* in_sizes, int n_in,
                              void* d_out, int out_size) {
    (void)in_sizes; (void)n_in; (void)out_size;
    const float* inputs = (const float*)d_in[0];
    const float* emb    = (const float*)d_in[1];
    const float* w0     = (const float*)d_in[2];
    const float* b0     = (const float*)d_in[3];
    const float* w1     = (const float*)d_in[4];
    const float* b1     = (const float*)d_in[5];
    const float* outw   = (const float*)d_in[6];
    const float* outb   = (const float*)d_in[7];
    float* out = (float*)d_out;

    __half *inph, *embs, *H0, *H1, *embT, *w0xT, *w0hT, *w1xT, *w1hT, *owT;
    float *X;
    int *ctr;
    cudaGetSymbolAddress((void**)&inph, g_inph);
    cudaGetSymbolAddress((void**)&embs, g_embs);
    cudaGetSymbolAddress((void**)&X,    g_X);
    cudaGetSymbolAddress((void**)&H0,   g_H0);
    cudaGetSymbolAddress((void**)&H1,   g_H1);
    cudaGetSymbolAddress((void**)&embT, g_embT);
    cudaGetSymbolAddress((void**)&w0xT, g_w0xT);
    cudaGetSymbolAddress((void**)&w0hT, g_w0hT);
    cudaGetSymbolAddress((void**)&w1xT, g_w1xT);
    cudaGetSymbolAddress((void**)&w1hT, g_w1hT);
    cudaGetSymbolAddress((void**)&owT,  g_owT);
    cudaGetSymbolAddress((void**)&ctr,  g_ctr);

    cudaFuncSetAttribute(lstm_layer,     cudaFuncAttributeMaxDynamicSharedMemorySize, LSTM_SMEM);
    cudaFuncSetAttribute(gemm16<float>,  cudaFuncAttributeMaxDynamicSharedMemorySize, GEMM_SMEM);
    cudaFuncSetAttribute(gemm16<__half>, cudaFuncAttributeMaxDynamicSharedMemorySize, GEMM_SMEM);

    // prep
    f2h_kernel<<<1024, 256>>>(inputs, inph, TB * VV);
    {
        dim3 blk(32, 8);
        transpose_cvt<<<dim3(VV/32, EE/32), blk>>>(emb,                EE, embT, VV, EE);
        transpose_cvt<<<dim3(EE/32, G4/32), blk>>>(w0,                 G4, w0xT, EE, G4);
        transpose_cvt<<<dim3(NH/32, G4/32), blk>>>(w0 + (size_t)EE*G4, G4, w0hT, NH, G4);
        transpose_cvt<<<dim3(NH/32, G4/32), blk>>>(w1,                 G4, w1xT, NH, G4);
        transpose_cvt<<<dim3(NH/32, G4/32), blk>>>(w1 + (size_t)NH*G4, G4, w1hT, NH, G4);
        transpose_cvt<<<dim3(NH/32, VV/32), blk>>>(outw,               VV, owT,  NH, VV);
    }
    zero_i<<<1, 32>>>(ctr);

    // embs = inputs @ emb
    gemm16<__half><<<dim3(EE/128, TB/128), 256, GEMM_SMEM>>>(inph, VV, embT, embs, EE, nullptr, TB, EE, VV);
    // X = embs @ W0x + b0
    gemm16<float><<<dim3(G4/128, TB/128), 256, GEMM_SMEM>>>(embs, EE, w0xT, X, G4, b0, TB, G4, EE);
    // layer 0 (persistent)
    lstm_layer<<<128, 256, LSTM_SMEM>>>(w0hT, X, H0, ctr);
    // X = H0 @ W1x + b1
    gemm16<float><<<dim3(G4/128, TB/128), 256, GEMM_SMEM>>>(H0, NH, w1xT, X, G4, b1, TB, G4, NH);
    // layer 1 (persistent)
    lstm_layer<<<128, 256, LSTM_SMEM>>>(w1hT, X, H1, ctr + 1);
    // logits = H1 @ out_w + out_b
    gemm16<float><<<dim3(VV/128, TB/128), 256, GEMM_SMEM>>>(H1, NH, owT, out, VV, outb, TB, VV, NH);
}

// round 15
// speedup vs baseline: 1.1735x; 1.1735x over previous
#include <cuda_runtime.h>
#include <cuda_fp16.h>
#include <stdint.h>

#define TT 256
#define BB 128
#define VV 256
#define EE 512
#define NH 1024
#define TB (TT*BB)          // 32768
#define G4 (4*NH)           // 4096

// ---------------- static device scratch ----------------
__device__ __align__(16) __half g_inph[(size_t)TB*VV];
__device__ __align__(16) __half g_embs[(size_t)TB*EE];
__device__ __align__(16) float  g_X[(size_t)TB*G4];
__device__ __align__(16) __half g_H0[(size_t)TB*NH];
__device__ __align__(16) __half g_H1[(size_t)TB*NH];
__device__ __align__(16) __half g_embT[EE*VV];           // [512][256]
__device__ __align__(16) __half g_w0xT[(size_t)G4*EE];   // [4096][512]
__device__ __align__(16) __half g_w0hT[(size_t)G4*NH];   // [4096][1024]
__device__ __align__(16) __half g_w1xT[(size_t)G4*NH];   // [4096][1024]
__device__ __align__(16) __half g_w1hT[(size_t)G4*NH];   // [4096][1024]
__device__ __align__(16) __half g_owT[VV*NH];            // [256][1024]
__device__ int g_ctr[4];                                 // [layer][bm-group]

// ---------------- helpers ----------------
__device__ __forceinline__ void mma16(float d[4], const unsigned a[4], const unsigned b[2]) {
    asm volatile(
        "mma.sync.aligned.m16n8k16.row.col.f32.f16.f16.f32 "
        "{%0,%1,%2,%3}, {%4,%5,%6,%7}, {%8,%9}, {%0,%1,%2,%3};\n"
        : "+f"(d[0]), "+f"(d[1]), "+f"(d[2]), "+f"(d[3])
        : "r"(a[0]), "r"(a[1]), "r"(a[2]), "r"(a[3]), "r"(b[0]), "r"(b[1]));
}
__device__ __forceinline__ void ldsm_x4(unsigned r[4], const __half* p) {
    unsigned a = (unsigned)__cvta_generic_to_shared(p);
    asm volatile("ldmatrix.sync.aligned.m8n8.x4.shared.b16 {%0,%1,%2,%3}, [%4];\n"
        : "=r"(r[0]), "=r"(r[1]), "=r"(r[2]), "=r"(r[3]) : "r"(a));
}
__device__ __forceinline__ void cpa16(__half* dst, const __half* src) {
    unsigned d = (unsigned)__cvta_generic_to_shared(dst);
    asm volatile("cp.async.cg.shared.global [%0], [%1], 16;\n" :: "r"(d), "l"(src));
}
#define CPA_COMMIT() asm volatile("cp.async.commit_group;\n" ::: "memory")
template <int N> __device__ __forceinline__ void cpa_wait() {
    asm volatile("cp.async.wait_group %0;\n" :: "n"(N) : "memory");
}
__device__ __forceinline__ void cstore2(float* C, size_t i, float a, float b) {
    *(float2*)&C[i] = make_float2(a, b);
}
__device__ __forceinline__ void cstore2(__half* C, size_t i, float a, float b) {
    *(__half2*)&C[i] = __floats2half2_rn(a, b);
}
__device__ __forceinline__ float sigf(float x) { return 1.f / (1.f + __expf(-x)); }

__global__ void zero_i(int* p) { if (threadIdx.x < 4) p[threadIdx.x] = 0; }
__global__ void f2h_kernel(const float* __restrict__ s, __half* __restrict__ d, int n) {
    for (int i = blockIdx.x * blockDim.x + threadIdx.x; i < n; i += gridDim.x * blockDim.x)
        d[i] = __float2half(s[i]);
}
// src fp32 [K][N] (row stride lds) -> dst fp16 [N][K]
__global__ void transpose_cvt(const float* __restrict__ src, int lds,
                              __half* __restrict__ dst, int K, int N) {
    __shared__ float tile[32][33];
    int kb = blockIdx.x * 32, nb = blockIdx.y * 32;
    #pragma unroll
    for (int i = threadIdx.y; i < 32; i += 8) {
        int k = kb + i, n = nb + threadIdx.x;
        tile[i][threadIdx.x] = (k < K && n < N) ? src[(size_t)k * lds + n] : 0.f;
    }
    __syncthreads();
    #pragma unroll
    for (int i = threadIdx.y; i < 32; i += 8) {
        int n = nb + i, k = kb + threadIdx.x;
        if (n < N && k < K) dst[(size_t)n * K + k] = __float2half(tile[threadIdx.x][i]);
    }
}

// ---------------- fp16 GEMM (validated R7): C = A @ Bt^T (+bias), 128x128 tile ----------------
#define GAST (128*40)
#define GBST (128*40)
#define GEMM_SMEM ((4*(GAST+GBST))*2)

template <typename TOUT>
__global__ void __launch_bounds__(256, 2) gemm16(
    const __half* __restrict__ A, int lda,
    const __half* __restrict__ Bt,
    TOUT* __restrict__ C, int ldc,
    const float* __restrict__ bias,
    int M, int N, int K)
{
    extern __shared__ __half sm[];
    __half* As = sm;
    __half* Bs = sm + 4*GAST;

    const int tid = threadIdx.x;
    const int bm = blockIdx.y * 128, bn = blockIdx.x * 128;
    const int wid = tid >> 5, lane = tid & 31;
    const int wr = (wid & 1) * 64, wc = (wid >> 1) * 32;
    const int r = lane >> 2, cl = lane & 3;

    float acc[4][4][4];
    #pragma unroll
    for (int i = 0; i < 4; ++i)
        #pragma unroll
        for (int j = 0; j < 4; ++j)
            #pragma unroll
            for (int k = 0; k < 4; ++k) acc[i][j][k] = 0.f;

    auto loadG = [&](int s, int kt) {
        #pragma unroll
        for (int i = 0; i < 2; ++i) {
            int idx = tid + i * 256;
            int row = idx >> 2, cc = idx & 3;
            cpa16(As + s*GAST + row*40 + cc*8,
                  A + (size_t)(bm + row) * lda + kt*32 + cc*8);
            cpa16(Bs + s*GBST + row*40 + cc*8,
                  Bt + (size_t)(bn + row) * K + kt*32 + cc*8);
        }
    };

    const int ktiles = K >> 5;
    #pragma unroll
    for (int s = 0; s < 3; ++s) { if (s < ktiles) loadG(s, s); CPA_COMMIT(); }

    const int a_row = (lane & 15);
    const int a_col = (lane >> 4) << 3;
    const int b_row = (lane & 7) + ((lane >> 4) << 3);
    const int b_col = (lane & 8);

    for (int kt = 0; kt < ktiles; ++kt) {
        cpa_wait<2>();
        __syncthreads();
        if (kt + 3 < ktiles) loadG((kt + 3) & 3, kt + 3);
        CPA_COMMIT();

        const __half* sA = As + (kt & 3) * GAST;
        const __half* sB = Bs + (kt & 3) * GBST;
        #pragma unroll
        for (int ks = 0; ks < 2; ++ks) {
            const int k0 = ks * 16;
            unsigned af[4][4], bf01[4], bf23[4];
            #pragma unroll
            for (int mt = 0; mt < 4; ++mt)
                ldsm_x4(af[mt], sA + (wr + mt*16 + a_row)*40 + k0 + a_col);
            ldsm_x4(bf01, sB + (wc      + b_row)*40 + k0 + b_col);
            ldsm_x4(bf23, sB + (wc + 16 + b_row)*40 + k0 + b_col);
            #pragma unroll
            for (int mt = 0; mt < 4; ++mt) {
                mma16(acc[mt][0], af[mt], bf01 + 0);
                mma16(acc[mt][1], af[mt], bf01 + 2);
                mma16(acc[mt][2], af[mt], bf23 + 0);
                mma16(acc[mt][3], af[mt], bf23 + 2);
            }
        }
    }

    #pragma unroll
    for (int mt = 0; mt < 4; ++mt)
        #pragma unroll
        for (int nt = 0; nt < 4; ++nt) {
            const int row = bm + wr + mt*16 + r;
            const int col = bn + wc + nt*8 + 2*cl;
            const float b0 = bias ? bias[col]     : 0.f;
            const float b1 = bias ? bias[col + 1] : 0.f;
            cstore2(C, (size_t)row * ldc + col,       acc[mt][nt][0] + b0, acc[mt][nt][1] + b1);
            cstore2(C, (size_t)(row + 8) * ldc + col, acc[mt][nt][2] + b0, acc[mt][nt][3] + b1);
        }
}

// ---------------- persistent LSTM layer kernel (2-D decomposition) ----------------
// 128 CTAs = 64 N-groups x 2 M-groups. CTA (bn = bx&63, bm = bx>>6) computes
// batch rows [bm*64, +64) x hidden cols [bn*16, +16) x 4 gates:
// GEMM M=64, N=64, K=1024. W slice (128KB, n = half*32 + gate*8 + j) resident.
// h-read per CTA = 64 rows (halves chip L2 broadcast vs 1-D split).
// 8 warps = 4 M-tiles x 2 N-halves; warp tile 16 rows x (4 gates x 8 cols).
// The two bm-groups are fully independent: per-group counter (64 arrivals).
#define BST2 (64*1032)
#define AST3 (64*136)
#define XS_OFF2 ((BST2 + 3*AST3)*2)           // byte offset of X stage (fp32 [64][68])
#define LSTM_SMEM2 (XS_OFF2 + 64*68*4)        // 201728 B

__global__ void __launch_bounds__(256, 1) lstm_layer(
    const __half* __restrict__ WhT,    // [4096][1024]
    const float*  __restrict__ X,      // [T*128][4096]
    __half* __restrict__ H,            // [T*128][1024]
    int* __restrict__ ctr)             // 2 ints (one per bm-group)
{
    extern __shared__ __half sm[];
    __half* Bs = sm;                   // 64 x 1032 (n = half*32 + gate*8 + j)
    __half* As = sm + BST2;            // 3 stages x 64 x 136
    float*  Xs = (float*)((char*)sm + XS_OFF2);   // 64 x 68 fp32

    const int tid = threadIdx.x, lane = tid & 31, wid = tid >> 5;
    const int r = lane >> 2, cl = lane & 3;
    const int bx = blockIdx.x;
    const int bn = bx & 63, bm = bx >> 6;
    const int mw = wid >> 1, wn = wid & 1;
    const int wr = mw * 16;
    const int jj = 2 * cl;
    const int gcol = bn * 16 + wn * 8 + jj;
    int* myctr = ctr + bm;

    // load W slice once: n = half*32 + gate*8 + j <- WhT row gate*1024 + bn*16 + half*8 + j
    #pragma unroll
    for (int i = 0; i < 32; ++i) {
        int idx = tid + i * 256;            // 0..8191 (16B units)
        int n = idx >> 7, cu = idx & 127;
        int half = n >> 5, gate = (n >> 3) & 3, j = n & 7;
        cpa16(Bs + n*1032 + cu*8,
              WhT + (size_t)(gate*1024 + bn*16 + half*8 + j) * 1024 + cu*8);
    }
    CPA_COMMIT();
    cpa_wait<0>();
    __syncthreads();

    float c0 = 0.f, c1 = 0.f, c2 = 0.f, c3 = 0.f;

    // A chunk: 64 rows (global bm*64+row) x 128 halfs of k (16KB), stride 136
    auto loadA = [&](__half* dst, const __half* hsrc, int ch) {
        #pragma unroll
        for (int i = 0; i < 4; ++i) {
            int idx = tid + i * 256;        // 0..1023 (16B units)
            int row = idx >> 4, cu = idx & 15;
            cpa16(dst + row*136 + cu*8,
                  hsrc + (size_t)(bm*64 + row)*1024 + ch*128 + cu*8);
        }
    };
    // stage X gate block [64 rows][4 gates x 16 cols] -> Xs[row][gate*16 + c]
    auto loadX = [&](const float* Xt) {
        #pragma unroll
        for (int i = 0; i < 4; ++i) {
            int u = tid + i * 256;          // 0..1023 (16B granules)
            int rr = u >> 4, seg = u & 15;  // seg = gate*4 + quad
            int g = seg >> 2, q = seg & 3;
            cpa16((__half*)(Xs + rr*68 + g*16 + q*4),
                  (const __half*)(Xt + (size_t)(bm*64 + rr)*4096 + g*1024 + bn*16 + q*4));
        }
    };

    for (int t = 0; t < TT; ++t) {
        float acc[4][4];
        #pragma unroll
        for (int i = 0; i < 4; ++i)
            #pragma unroll
            for (int j = 0; j < 4; ++j) acc[i][j] = 0.f;

        const float* Xt = X + (size_t)t * (BB * G4);

        if (t > 0) {
            const __half* hsrc = H + (size_t)(t - 1) * BB * NH;
            loadA(As + 0*AST3, hsrc, 0); loadX(Xt); CPA_COMMIT();
            loadA(As + 1*AST3, hsrc, 1); CPA_COMMIT();

            #pragma unroll 1
            for (int kt = 0; kt < 8; ++kt) {
                if (kt < 7) cpa_wait<1>(); else cpa_wait<0>();
                __syncthreads();
                if (kt + 2 < 8) {
                    int st = kt + 2; st -= (st >= 3) ? 3 : 0; st -= (st >= 3) ? 3 : 0;
                    loadA(As + st * AST3, hsrc, kt + 2);
                }
                CPA_COMMIT();

                int sb = kt; sb -= (sb >= 3) ? 3 : 0; sb -= (sb >= 3) ? 3 : 0;
                const __half* sA = As + sb * AST3;
                #pragma unroll
                for (int ks = 0; ks < 8; ++ks) {
                    const int k0 = ks * 16;
                    unsigned af[4];
                    af[0] = *(const unsigned*)&sA[(wr + r    )*136 + k0 + jj];
                    af[1] = *(const unsigned*)&sA[(wr + r + 8)*136 + k0 + jj];
                    af[2] = *(const unsigned*)&sA[(wr + r    )*136 + k0 + jj + 8];
                    af[3] = *(const unsigned*)&sA[(wr + r + 8)*136 + k0 + jj + 8];
                    #pragma unroll
                    for (int nt = 0; nt < 4; ++nt) {
                        const __half* bp = Bs + (size_t)(wn*32 + nt*8 + r)*1032
                                              + kt*128 + k0 + jj;
                        unsigned bf[2];
                        bf[0] = *(const unsigned*)bp;
                        bf[1] = *(const unsigned*)(bp + 8);
                        mma16(acc[nt], af, bf);
                    }
                }
            }
        } else {
            loadX(Xt); CPA_COMMIT();
            cpa_wait<0>();
            __syncthreads();   // publish Xs before epilogue reads
        }

        // gates + state update, all in registers (X from smem stage)
        const int rl0 = wr + r, rl1 = rl0 + 8;
        const int grow0 = bm*64 + rl0, grow1 = bm*64 + rl1;
        {
            const float* xa = Xs + rl0*68 + wn*8 + jj;
            float2 xf = *(const float2*)(xa);
            float2 xi = *(const float2*)(xa + 16);
            float2 xo = *(const float2*)(xa + 32);
            float2 xg = *(const float2*)(xa + 48);
            float f  = sigf(acc[0][0] + xf.x), ig  = sigf(acc[1][0] + xi.x);
            float o  = sigf(acc[2][0] + xo.x), gg  = tanhf(acc[3][0] + xg.x);
            c0 = f * c0 + ig * gg;
            float f1 = sigf(acc[0][1] + xf.y), ig1 = sigf(acc[1][1] + xi.y);
            float o1 = sigf(acc[2][1] + xo.y), gg1 = tanhf(acc[3][1] + xg.y);
            c1 = f1 * c1 + ig1 * gg1;
            __half2 hv = __floats2half2_rn(o * tanhf(c0), o1 * tanhf(c1));
            *(__half2*)&H[(size_t)t*BB*NH + (size_t)grow0*1024 + gcol] = hv;
        }
        {
            const float* xb = Xs + rl1*68 + wn*8 + jj;
            float2 xf = *(const float2*)(xb);
            float2 xi = *(const float2*)(xb + 16);
            float2 xo = *(const float2*)(xb + 32);
            float2 xg = *(const float2*)(xb + 48);
            float f  = sigf(acc[0][2] + xf.x), ig  = sigf(acc[1][2] + xi.x);
            float o  = sigf(acc[2][2] + xo.x), gg  = tanhf(acc[3][2] + xg.x);
            c2 = f * c2 + ig * gg;
            float f1 = sigf(acc[0][3] + xf.y), ig1 = sigf(acc[1][3] + xi.y);
            float o1 = sigf(acc[2][3] + xo.y), gg1 = tanhf(acc[3][3] + xg.y);
            c3 = f1 * c3 + ig1 * gg1;
            __half2 hv = __floats2half2_rn(o * tanhf(c2), o1 * tanhf(c3));
            *(__half2*)&H[(size_t)t*BB*NH + (size_t)grow1*1024 + gcol] = hv;
        }

        if (t + 1 < TT) {
            __syncthreads();       // all CTA threads' H stores happen-before tid0's release
            if (tid == 0) {
                asm volatile("red.release.gpu.global.add.u32 [%0], %1;"
                             :: "l"(myctr), "r"(1) : "memory");
                const int target = 64 * (t + 1);
                int v;
                while (true) {
                    asm volatile("ld.acquire.gpu.b32 %0, [%1];" : "=r"(v) : "l"(myctr));
                    if (v >= target) break;
                    __nanosleep(64);   // backoff
                }
            }
            __syncthreads();       // broadcast acquire to whole CTA
        }
    }
}

// ---------------- launch ----------------
extern "C" void kernel_launch(void* const* d_in, const int* in_sizes, int n_in,
                              void* d_out, int out_size) {
    (void)in_sizes; (void)n_in; (void)out_size;
    const float* inputs = (const float*)d_in[0];
    const float* emb    = (const float*)d_in[1];
    const float* w0     = (const float*)d_in[2];
    const float* b0     = (const float*)d_in[3];
    const float* w1     = (const float*)d_in[4];
    const float* b1     = (const float*)d_in[5];
    const float* outw   = (const float*)d_in[6];
    const float* outb   = (const float*)d_in[7];
    float* out = (float*)d_out;

    __half *inph, *embs, *H0, *H1, *embT, *w0xT, *w0hT, *w1xT, *w1hT, *owT;
    float *X;
    int *ctr;
    cudaGetSymbolAddress((void**)&inph, g_inph);
    cudaGetSymbolAddress((void**)&embs, g_embs);
    cudaGetSymbolAddress((void**)&X,    g_X);
    cudaGetSymbolAddress((void**)&H0,   g_H0);
    cudaGetSymbolAddress((void**)&H1,   g_H1);
    cudaGetSymbolAddress((void**)&embT, g_embT);
    cudaGetSymbolAddress((void**)&w0xT, g_w0xT);
    cudaGetSymbolAddress((void**)&w0hT, g_w0hT);
    cudaGetSymbolAddress((void**)&w1xT, g_w1xT);
    cudaGetSymbolAddress((void**)&w1hT, g_w1hT);
    cudaGetSymbolAddress((void**)&owT,  g_owT);
    cudaGetSymbolAddress((void**)&ctr,  g_ctr);

    cudaFuncSetAttribute(lstm_layer,     cudaFuncAttributeMaxDynamicSharedMemorySize, LSTM_SMEM2);
    cudaFuncSetAttribute(gemm16<float>,  cudaFuncAttributeMaxDynamicSharedMemorySize, GEMM_SMEM);
    cudaFuncSetAttribute(gemm16<__half>, cudaFuncAttributeMaxDynamicSharedMemorySize, GEMM_SMEM);

    // prep
    f2h_kernel<<<1024, 256>>>(inputs, inph, TB * VV);
    {
        dim3 blk(32, 8);
        transpose_cvt<<<dim3(VV/32, EE/32), blk>>>(emb,                EE, embT, VV, EE);
        transpose_cvt<<<dim3(EE/32, G4/32), blk>>>(w0,                 G4, w0xT, EE, G4);
        transpose_cvt<<<dim3(NH/32, G4/32), blk>>>(w0 + (size_t)EE*G4, G4, w0hT, NH, G4);
        transpose_cvt<<<dim3(NH/32, G4/32), blk>>>(w1,                 G4, w1xT, NH, G4);
        transpose_cvt<<<dim3(NH/32, G4/32), blk>>>(w1 + (size_t)NH*G4, G4, w1hT, NH, G4);
        transpose_cvt<<<dim3(NH/32, VV/32), blk>>>(outw,               VV, owT,  NH, VV);
    }
    zero_i<<<1, 32>>>(ctr);

    // embs = inputs @ emb
    gemm16<__half><<<dim3(EE/128, TB/128), 256, GEMM_SMEM>>>(inph, VV, embT, embs, EE, nullptr, TB, EE, VV);
    // X = embs @ W0x + b0
    gemm16<float><<<dim3(G4/128, TB/128), 256, GEMM_SMEM>>>(embs, EE, w0xT, X, G4, b0, TB, G4, EE);
    // layer 0 (persistent, 2-D split)
    lstm_layer<<<128, 256, LSTM_SMEM2>>>(w0hT, X, H0, ctr);
    // X = H0 @ W1x + b1
    gemm16<float><<<dim3(G4/128, TB/128), 256, GEMM_SMEM>>>(H0, NH, w1xT, X, G4, b1, TB, G4, NH);
    // layer 1 (persistent, 2-D split)
    lstm_layer<<<128, 256, LSTM_SMEM2>>>(w1hT, X, H1, ctr + 2);
    // logits = H1 @ out_w + out_b
    gemm16<float><<<dim3(VV/128, TB/128), 256, GEMM_SMEM>>>(H1, NH, owT, out, VV, outb, TB, VV, NH);
}

// round 16
// speedup vs baseline: 1.1930x; 1.0167x over previous
#include <cuda_runtime.h>
#include <cuda_fp16.h>
#include <stdint.h>

#define TT 256
#define BB 128
#define VV 256
#define EE 512
#define NH 1024
#define TB (TT*BB)          // 32768
#define G4 (4*NH)           // 4096

// ---------------- static device scratch ----------------
__device__ __align__(16) __half g_inph[(size_t)TB*VV];
__device__ __align__(16) __half g_embs[(size_t)TB*EE];
__device__ __align__(16) __half g_X[(size_t)TB*G4];      // fp16 gate inputs
__device__ __align__(16) __half g_H0[(size_t)TB*NH];
__device__ __align__(16) __half g_H1[(size_t)TB*NH];
__device__ __align__(16) __half g_embT[EE*VV];           // [512][256]
__device__ __align__(16) __half g_w0xT[(size_t)G4*EE];   // [4096][512]
__device__ __align__(16) __half g_w0hT[(size_t)G4*NH];   // [4096][1024]
__device__ __align__(16) __half g_w1xT[(size_t)G4*NH];   // [4096][1024]
__device__ __align__(16) __half g_w1hT[(size_t)G4*NH];   // [4096][1024]
__device__ __align__(16) __half g_owT[VV*NH];            // [256][1024]
__device__ int g_ctr[4];                                 // [layer][bm-group]

// ---------------- helpers ----------------
__device__ __forceinline__ void mma16(float d[4], const unsigned a[4], const unsigned b[2]) {
    asm volatile(
        "mma.sync.aligned.m16n8k16.row.col.f32.f16.f16.f32 "
        "{%0,%1,%2,%3}, {%4,%5,%6,%7}, {%8,%9}, {%0,%1,%2,%3};\n"
        : "+f"(d[0]), "+f"(d[1]), "+f"(d[2]), "+f"(d[3])
        : "r"(a[0]), "r"(a[1]), "r"(a[2]), "r"(a[3]), "r"(b[0]), "r"(b[1]));
}
__device__ __forceinline__ void ldsm_x4(unsigned r[4], const __half* p) {
    unsigned a = (unsigned)__cvta_generic_to_shared(p);
    asm volatile("ldmatrix.sync.aligned.m8n8.x4.shared.b16 {%0,%1,%2,%3}, [%4];\n"
        : "=r"(r[0]), "=r"(r[1]), "=r"(r[2]), "=r"(r[3]) : "r"(a));
}
__device__ __forceinline__ void cpa16(__half* dst, const __half* src) {
    unsigned d = (unsigned)__cvta_generic_to_shared(dst);
    asm volatile("cp.async.cg.shared.global [%0], [%1], 16;\n" :: "r"(d), "l"(src));
}
#define CPA_COMMIT() asm volatile("cp.async.commit_group;\n" ::: "memory")
template <int N> __device__ __forceinline__ void cpa_wait() {
    asm volatile("cp.async.wait_group %0;\n" :: "n"(N) : "memory");
}
__device__ __forceinline__ void cstore2(float* C, size_t i, float a, float b) {
    *(float2*)&C[i] = make_float2(a, b);
}
__device__ __forceinline__ void cstore2(__half* C, size_t i, float a, float b) {
    *(__half2*)&C[i] = __floats2half2_rn(a, b);
}
__device__ __forceinline__ float sigf(float x) { return 1.f / (1.f + __expf(-x)); }

__global__ void zero_i(int* p) { if (threadIdx.x < 4) p[threadIdx.x] = 0; }
__global__ void f2h_kernel(const float* __restrict__ s, __half* __restrict__ d, int n) {
    for (int i = blockIdx.x * blockDim.x + threadIdx.x; i < n; i += gridDim.x * blockDim.x)
        d[i] = __float2half(s[i]);
}
// src fp32 [K][N] (row stride lds) -> dst fp16 [N][K]
__global__ void transpose_cvt(const float* __restrict__ src, int lds,
                              __half* __restrict__ dst, int K, int N) {
    __shared__ float tile[32][33];
    int kb = blockIdx.x * 32, nb = blockIdx.y * 32;
    #pragma unroll
    for (int i = threadIdx.y; i < 32; i += 8) {
        int k = kb + i, n = nb + threadIdx.x;
        tile[i][threadIdx.x] = (k < K && n < N) ? src[(size_t)k * lds + n] : 0.f;
    }
    __syncthreads();
    #pragma unroll
    for (int i = threadIdx.y; i < 32; i += 8) {
        int n = nb + i, k = kb + threadIdx.x;
        if (n < N && k < K) dst[(size_t)n * K + k] = __float2half(tile[threadIdx.x][i]);
    }
}

// ---------------- fp16 GEMM (validated R7): C = A @ Bt^T (+bias), 128x128 tile ----------------
#define GAST (128*40)
#define GBST (128*40)
#define GEMM_SMEM ((4*(GAST+GBST))*2)

template <typename TOUT>
__global__ void __launch_bounds__(256, 2) gemm16(
    const __half* __restrict__ A, int lda,
    const __half* __restrict__ Bt,
    TOUT* __restrict__ C, int ldc,
    const float* __restrict__ bias,
    int M, int N, int K)
{
    extern __shared__ __half sm[];
    __half* As = sm;
    __half* Bs = sm + 4*GAST;

    const int tid = threadIdx.x;
    const int bm = blockIdx.y * 128, bn = blockIdx.x * 128;
    const int wid = tid >> 5, lane = tid & 31;
    const int wr = (wid & 1) * 64, wc = (wid >> 1) * 32;
    const int r = lane >> 2, cl = lane & 3;

    float acc[4][4][4];
    #pragma unroll
    for (int i = 0; i < 4; ++i)
        #pragma unroll
        for (int j = 0; j < 4; ++j)
            #pragma unroll
            for (int k = 0; k < 4; ++k) acc[i][j][k] = 0.f;

    auto loadG = [&](int s, int kt) {
        #pragma unroll
        for (int i = 0; i < 2; ++i) {
            int idx = tid + i * 256;
            int row = idx >> 2, cc = idx & 3;
            cpa16(As + s*GAST + row*40 + cc*8,
                  A + (size_t)(bm + row) * lda + kt*32 + cc*8);
            cpa16(Bs + s*GBST + row*40 + cc*8,
                  Bt + (size_t)(bn + row) * K + kt*32 + cc*8);
        }
    };

    const int ktiles = K >> 5;
    #pragma unroll
    for (int s = 0; s < 3; ++s) { if (s < ktiles) loadG(s, s); CPA_COMMIT(); }

    const int a_row = (lane & 15);
    const int a_col = (lane >> 4) << 3;
    const int b_row = (lane & 7) + ((lane >> 4) << 3);
    const int b_col = (lane & 8);

    for (int kt = 0; kt < ktiles; ++kt) {
        cpa_wait<2>();
        __syncthreads();
        if (kt + 3 < ktiles) loadG((kt + 3) & 3, kt + 3);
        CPA_COMMIT();

        const __half* sA = As + (kt & 3) * GAST;
        const __half* sB = Bs + (kt & 3) * GBST;
        #pragma unroll
        for (int ks = 0; ks < 2; ++ks) {
            const int k0 = ks * 16;
            unsigned af[4][4], bf01[4], bf23[4];
            #pragma unroll
            for (int mt = 0; mt < 4; ++mt)
                ldsm_x4(af[mt], sA + (wr + mt*16 + a_row)*40 + k0 + a_col);
            ldsm_x4(bf01, sB + (wc      + b_row)*40 + k0 + b_col);
            ldsm_x4(bf23, sB + (wc + 16 + b_row)*40 + k0 + b_col);
            #pragma unroll
            for (int mt = 0; mt < 4; ++mt) {
                mma16(acc[mt][0], af[mt], bf01 + 0);
                mma16(acc[mt][1], af[mt], bf01 + 2);
                mma16(acc[mt][2], af[mt], bf23 + 0);
                mma16(acc[mt][3], af[mt], bf23 + 2);
            }
        }
    }

    #pragma unroll
    for (int mt = 0; mt < 4; ++mt)
        #pragma unroll
        for (int nt = 0; nt < 4; ++nt) {
            const int row = bm + wr + mt*16 + r;
            const int col = bn + wc + nt*8 + 2*cl;
            const float b0 = bias ? bias[col]     : 0.f;
            const float b1 = bias ? bias[col + 1] : 0.f;
            cstore2(C, (size_t)row * ldc + col,       acc[mt][nt][0] + b0, acc[mt][nt][1] + b1);
            cstore2(C, (size_t)(row + 8) * ldc + col, acc[mt][nt][2] + b0, acc[mt][nt][3] + b1);
        }
}

// ---------------- persistent LSTM layer kernel (2-D decomposition, fp16 X) ----------------
// 128 CTAs = 64 N-groups x 2 M-groups. CTA (bn = bx&63, bm = bx>>6) computes
// batch rows [bm*64, +64) x hidden cols [bn*16, +16) x 4 gates:
// GEMM M=64, N=64, K=1024. W slice (128KB, n = half*32 + gate*8 + j) resident.
// 8 warps = 4 M-tiles x 2 N-halves; warp tile 16 rows x (4 gates x 8 cols).
// The two bm-groups are fully independent: per-group counter (64 arrivals).
#define BST2 (64*1032)
#define AST3 (64*136)
#define XS_OFF2 ((BST2 + 3*AST3)*2)           // byte offset of X stage (fp16 [64][80])
#define LSTM_SMEM2 (XS_OFF2 + 64*80*2)

__global__ void __launch_bounds__(256, 1) lstm_layer(
    const __half* __restrict__ WhT,    // [4096][1024]
    const __half* __restrict__ X,      // [T*128][4096] fp16
    __half* __restrict__ H,            // [T*128][1024]
    int* __restrict__ ctr)             // 2 ints (one per bm-group)
{
    extern __shared__ __half sm[];
    __half* Bs = sm;                   // 64 x 1032 (n = half*32 + gate*8 + j)
    __half* As = sm + BST2;            // 3 stages x 64 x 136
    __half* Xsh = (__half*)((char*)sm + XS_OFF2);   // 64 x 80 fp16

    const int tid = threadIdx.x, lane = tid & 31, wid = tid >> 5;
    const int r = lane >> 2, cl = lane & 3;
    const int bx = blockIdx.x;
    const int bn = bx & 63, bm = bx >> 6;
    const int mw = wid >> 1, wn = wid & 1;
    const int wr = mw * 16;
    const int jj = 2 * cl;
    const int gcol = bn * 16 + wn * 8 + jj;
    int* myctr = ctr + bm;

    // load W slice once: n = half*32 + gate*8 + j <- WhT row gate*1024 + bn*16 + half*8 + j
    #pragma unroll
    for (int i = 0; i < 32; ++i) {
        int idx = tid + i * 256;            // 0..8191 (16B units)
        int n = idx >> 7, cu = idx & 127;
        int half = n >> 5, gate = (n >> 3) & 3, j = n & 7;
        cpa16(Bs + n*1032 + cu*8,
              WhT + (size_t)(gate*1024 + bn*16 + half*8 + j) * 1024 + cu*8);
    }
    CPA_COMMIT();
    cpa_wait<0>();
    __syncthreads();

    float c0 = 0.f, c1 = 0.f, c2 = 0.f, c3 = 0.f;

    // A chunk: 64 rows (global bm*64+row) x 128 halfs of k (16KB), stride 136
    auto loadA = [&](__half* dst, const __half* hsrc, int ch) {
        #pragma unroll
        for (int i = 0; i < 4; ++i) {
            int idx = tid + i * 256;        // 0..1023 (16B units)
            int row = idx >> 4, cu = idx & 15;
            cpa16(dst + row*136 + cu*8,
                  hsrc + (size_t)(bm*64 + row)*1024 + ch*128 + cu*8);
        }
    };
    // stage X gate block [64 rows][4 gates x 16 cols] fp16 -> Xsh[row][gate*16 + c]
    auto loadX = [&](const __half* Xt) {
        #pragma unroll
        for (int i = 0; i < 2; ++i) {
            int u = tid + i * 256;          // 0..511 (16B granules)
            int rr = u >> 3, seg = u & 7;   // seg = gate*2 + q
            int g = seg >> 1, q = seg & 1;
            cpa16(Xsh + rr*80 + g*16 + q*8,
                  Xt + (size_t)(bm*64 + rr)*4096 + g*1024 + bn*16 + q*8);
        }
    };

    for (int t = 0; t < TT; ++t) {
        float acc[4][4];
        #pragma unroll
        for (int i = 0; i < 4; ++i)
            #pragma unroll
            for (int j = 0; j < 4; ++j) acc[i][j] = 0.f;

        const __half* Xt = X + (size_t)t * (BB * G4);

        if (t > 0) {
            const __half* hsrc = H + (size_t)(t - 1) * BB * NH;
            loadA(As + 0*AST3, hsrc, 0); loadX(Xt); CPA_COMMIT();
            loadA(As + 1*AST3, hsrc, 1); CPA_COMMIT();

            #pragma unroll 1
            for (int kt = 0; kt < 8; ++kt) {
                if (kt < 7) cpa_wait<1>(); else cpa_wait<0>();
                __syncthreads();
                if (kt + 2 < 8) {
                    int st = kt + 2; st -= (st >= 3) ? 3 : 0; st -= (st >= 3) ? 3 : 0;
                    loadA(As + st * AST3, hsrc, kt + 2);
                }
                CPA_COMMIT();

                int sb = kt; sb -= (sb >= 3) ? 3 : 0; sb -= (sb >= 3) ? 3 : 0;
                const __half* sA = As + sb * AST3;
                #pragma unroll
                for (int ks = 0; ks < 8; ++ks) {
                    const int k0 = ks * 16;
                    unsigned af[4];
                    af[0] = *(const unsigned*)&sA[(wr + r    )*136 + k0 + jj];
                    af[1] = *(const unsigned*)&sA[(wr + r + 8)*136 + k0 + jj];
                    af[2] = *(const unsigned*)&sA[(wr + r    )*136 + k0 + jj + 8];
                    af[3] = *(const unsigned*)&sA[(wr + r + 8)*136 + k0 + jj + 8];
                    #pragma unroll
                    for (int nt = 0; nt < 4; ++nt) {
                        const __half* bp = Bs + (size_t)(wn*32 + nt*8 + r)*1032
                                              + kt*128 + k0 + jj;
                        unsigned bf[2];
                        bf[0] = *(const unsigned*)bp;
                        bf[1] = *(const unsigned*)(bp + 8);
                        mma16(acc[nt], af, bf);
                    }
                }
            }
        } else {
            loadX(Xt); CPA_COMMIT();
            cpa_wait<0>();
            __syncthreads();   // publish Xsh before epilogue reads
        }

        // gates + state update, all in registers (X from fp16 smem stage)
        const int rl0 = wr + r, rl1 = rl0 + 8;
        const int grow0 = bm*64 + rl0, grow1 = bm*64 + rl1;
        {
            const __half* xa = Xsh + rl0*80 + wn*8 + jj;
            float2 xf = __half22float2(*(const __half2*)(xa));
            float2 xi = __half22float2(*(const __half2*)(xa + 16));
            float2 xo = __half22float2(*(const __half2*)(xa + 32));
            float2 xg = __half22float2(*(const __half2*)(xa + 48));
            float f  = sigf(acc[0][0] + xf.x), ig  = sigf(acc[1][0] + xi.x);
            float o  = sigf(acc[2][0] + xo.x), gg  = tanhf(acc[3][0] + xg.x);
            c0 = f * c0 + ig * gg;
            float f1 = sigf(acc[0][1] + xf.y), ig1 = sigf(acc[1][1] + xi.y);
            float o1 = sigf(acc[2][1] + xo.y), gg1 = tanhf(acc[3][1] + xg.y);
            c1 = f1 * c1 + ig1 * gg1;
            __half2 hv = __floats2half2_rn(o * tanhf(c0), o1 * tanhf(c1));
            *(__half2*)&H[(size_t)t*BB*NH + (size_t)grow0*1024 + gcol] = hv;
        }
        {
            const __half* xb = Xsh + rl1*80 + wn*8 + jj;
            float2 xf = __half22float2(*(const __half2*)(xb));
            float2 xi = __half22float2(*(const __half2*)(xb + 16));
            float2 xo = __half22float2(*(const __half2*)(xb + 32));
            float2 xg = __half22float2(*(const __half2*)(xb + 48));
            float f  = sigf(acc[0][2] + xf.x), ig  = sigf(acc[1][2] + xi.x);
            float o  = sigf(acc[2][2] + xo.x), gg  = tanhf(acc[3][2] + xg.x);
            c2 = f * c2 + ig * gg;
            float f1 = sigf(acc[0][3] + xf.y), ig1 = sigf(acc[1][3] + xi.y);
            float o1 = sigf(acc[2][3] + xo.y), gg1 = tanhf(acc[3][3] + xg.y);
            c3 = f1 * c3 + ig1 * gg1;
            __half2 hv = __floats2half2_rn(o * tanhf(c2), o1 * tanhf(c3));
            *(__half2*)&H[(size_t)t*BB*NH + (size_t)grow1*1024 + gcol] = hv;
        }

        if (t + 1 < TT) {
            __syncthreads();       // all CTA threads' H stores happen-before tid0's release
            if (tid == 0) {
                asm volatile("red.release.gpu.global.add.u32 [%0], %1;"
                             :: "l"(myctr), "r"(1) : "memory");
                const int target = 64 * (t + 1);
                int v;
                while (true) {
                    asm volatile("ld.acquire.gpu.b32 %0, [%1];" : "=r"(v) : "l"(myctr));
                    if (v >= target) break;
                    __nanosleep(64);   // backoff
                }
            }
            __syncthreads();       // broadcast acquire to whole CTA
        }
    }
}

// ---------------- launch ----------------
extern "C" void kernel_launch(void* const* d_in, const int* in_sizes, int n_in,
                              void* d_out, int out_size) {
    (void)in_sizes; (void)n_in; (void)out_size;
    const float* inputs = (const float*)d_in[0];
    const float* emb    = (const float*)d_in[1];
    const float* w0     = (const float*)d_in[2];
    const float* b0     = (const float*)d_in[3];
    const float* w1     = (const float*)d_in[4];
    const float* b1     = (const float*)d_in[5];
    const float* outw   = (const float*)d_in[6];
    const float* outb   = (const float*)d_in[7];
    float* out = (float*)d_out;

    __half *inph, *embs, *H0, *H1, *embT, *w0xT, *w0hT, *w1xT, *w1hT, *owT, *X;
    int *ctr;
    cudaGetSymbolAddress((void**)&inph, g_inph);
    cudaGetSymbolAddress((void**)&embs, g_embs);
    cudaGetSymbolAddress((void**)&X,    g_X);
    cudaGetSymbolAddress((void**)&H0,   g_H0);
    cudaGetSymbolAddress((void**)&H1,   g_H1);
    cudaGetSymbolAddress((void**)&embT, g_embT);
    cudaGetSymbolAddress((void**)&w0xT, g_w0xT);
    cudaGetSymbolAddress((void**)&w0hT, g_w0hT);
    cudaGetSymbolAddress((void**)&w1xT, g_w1xT);
    cudaGetSymbolAddress((void**)&w1hT, g_w1hT);
    cudaGetSymbolAddress((void**)&owT,  g_owT);
    cudaGetSymbolAddress((void**)&ctr,  g_ctr);

    cudaFuncSetAttribute(lstm_layer,     cudaFuncAttributeMaxDynamicSharedMemorySize, LSTM_SMEM2);
    cudaFuncSetAttribute(gemm16<float>,  cudaFuncAttributeMaxDynamicSharedMemorySize, GEMM_SMEM);
    cudaFuncSetAttribute(gemm16<__half>, cudaFuncAttributeMaxDynamicSharedMemorySize, GEMM_SMEM);

    // prep
    f2h_kernel<<<1024, 256>>>(inputs, inph, TB * VV);
    {
        dim3 blk(32, 8);
        transpose_cvt<<<dim3(VV/32, EE/32), blk>>>(emb,                EE, embT, VV, EE);
        transpose_cvt<<<dim3(EE/32, G4/32), blk>>>(w0,                 G4, w0xT, EE, G4);
        transpose_cvt<<<dim3(NH/32, G4/32), blk>>>(w0 + (size_t)EE*G4, G4, w0hT, NH, G4);
        transpose_cvt<<<dim3(NH/32, G4/32), blk>>>(w1,                 G4, w1xT, NH, G4);
        transpose_cvt<<<dim3(NH/32, G4/32), blk>>>(w1 + (size_t)NH*G4, G4, w1hT, NH, G4);
        transpose_cvt<<<dim3(NH/32, VV/32), blk>>>(outw,               VV, owT,  NH, VV);
    }
    zero_i<<<1, 32>>>(ctr);

    // embs = inputs @ emb
    gemm16<__half><<<dim3(EE/128, TB/128), 256, GEMM_SMEM>>>(inph, VV, embT, embs, EE, nullptr, TB, EE, VV);
    // X = embs @ W0x + b0   (fp16 store)
    gemm16<__half><<<dim3(G4/128, TB/128), 256, GEMM_SMEM>>>(embs, EE, w0xT, X, G4, b0, TB, G4, EE);
    // layer 0 (persistent, 2-D split)
    lstm_layer<<<128, 256, LSTM_SMEM2>>>(w0hT, X, H0, ctr);
    // X = H0 @ W1x + b1   (fp16 store)
    gemm16<__half><<<dim3(G4/128, TB/128), 256, GEMM_SMEM>>>(H0, NH, w1xT, X, G4, b1, TB, G4, NH);
    // layer 1 (persistent, 2-D split)
    lstm_layer<<<128, 256, LSTM_SMEM2>>>(w1hT, X, H1, ctr + 2);
    // logits = H1 @ out_w + out_b
    gemm16<float><<<dim3(VV/128, TB/128), 256, GEMM_SMEM>>>(H1, NH, owT, out, VV, outb, TB, VV, NH);
}

// round 17
// speedup vs baseline: 1.2156x; 1.0189x over previous
#include <cuda_runtime.h>
#include <cuda_fp16.h>
#include <stdint.h>

#define TT 256
#define BB 128
#define VV 256
#define EE 512
#define NH 1024
#define TB (TT*BB)          // 32768
#define G4 (4*NH)           // 4096

// ---------------- static device scratch ----------------
__device__ __align__(16) __half g_inph[(size_t)TB*VV];
__device__ __align__(16) __half g_embs[(size_t)TB*EE];
__device__ __align__(16) __half g_X[(size_t)TB*G4];      // fp16 gate inputs
__device__ __align__(16) __half g_H0[(size_t)TB*NH];
__device__ __align__(16) __half g_H1[(size_t)TB*NH];
__device__ __align__(16) __half g_embT[EE*VV];           // [512][256]
__device__ __align__(16) __half g_w0xT[(size_t)G4*EE];   // [4096][512]
__device__ __align__(16) __half g_w0hT[(size_t)G4*NH];   // [4096][1024]
__device__ __align__(16) __half g_w1xT[(size_t)G4*NH];   // [4096][1024]
__device__ __align__(16) __half g_w1hT[(size_t)G4*NH];   // [4096][1024]
__device__ __align__(16) __half g_owT[VV*NH];            // [256][1024]
__device__ int g_ctr[4];                                 // [layer][bm-group]

// ---------------- helpers ----------------
__device__ __forceinline__ void mma16(float d[4], const unsigned a[4], const unsigned b[2]) {
    asm volatile(
        "mma.sync.aligned.m16n8k16.row.col.f32.f16.f16.f32 "
        "{%0,%1,%2,%3}, {%4,%5,%6,%7}, {%8,%9}, {%0,%1,%2,%3};\n"
        : "+f"(d[0]), "+f"(d[1]), "+f"(d[2]), "+f"(d[3])
        : "r"(a[0]), "r"(a[1]), "r"(a[2]), "r"(a[3]), "r"(b[0]), "r"(b[1]));
}
__device__ __forceinline__ void ldsm_x4(unsigned r[4], const __half* p) {
    unsigned a = (unsigned)__cvta_generic_to_shared(p);
    asm volatile("ldmatrix.sync.aligned.m8n8.x4.shared.b16 {%0,%1,%2,%3}, [%4];\n"
        : "=r"(r[0]), "=r"(r[1]), "=r"(r[2]), "=r"(r[3]) : "r"(a));
}
__device__ __forceinline__ void cpa16(__half* dst, const __half* src) {
    unsigned d = (unsigned)__cvta_generic_to_shared(dst);
    asm volatile("cp.async.cg.shared.global [%0], [%1], 16;\n" :: "r"(d), "l"(src));
}
#define CPA_COMMIT() asm volatile("cp.async.commit_group;\n" ::: "memory")
template <int N> __device__ __forceinline__ void cpa_wait() {
    asm volatile("cp.async.wait_group %0;\n" :: "n"(N) : "memory");
}
__device__ __forceinline__ void cstore2(float* C, size_t i, float a, float b) {
    *(float2*)&C[i] = make_float2(a, b);
}
__device__ __forceinline__ void cstore2(__half* C, size_t i, float a, float b) {
    *(__half2*)&C[i] = __floats2half2_rn(a, b);
}
__device__ __forceinline__ float sigf(float x) { return 1.f / (1.f + __expf(-x)); }

__global__ void zero_i(int* p) { if (threadIdx.x < 4) p[threadIdx.x] = 0; }
__global__ void f2h_kernel(const float* __restrict__ s, __half* __restrict__ d, int n) {
    for (int i = blockIdx.x * blockDim.x + threadIdx.x; i < n; i += gridDim.x * blockDim.x)
        d[i] = __float2half(s[i]);
}
// src fp32 [K][N] (row stride lds) -> dst fp16 [N][K]
__global__ void transpose_cvt(const float* __restrict__ src, int lds,
                              __half* __restrict__ dst, int K, int N) {
    __shared__ float tile[32][33];
    int kb = blockIdx.x * 32, nb = blockIdx.y * 32;
    #pragma unroll
    for (int i = threadIdx.y; i < 32; i += 8) {
        int k = kb + i, n = nb + threadIdx.x;
        tile[i][threadIdx.x] = (k < K && n < N) ? src[(size_t)k * lds + n] : 0.f;
    }
    __syncthreads();
    #pragma unroll
    for (int i = threadIdx.y; i < 32; i += 8) {
        int n = nb + i, k = kb + threadIdx.x;
        if (n < N && k < K) dst[(size_t)n * K + k] = __float2half(tile[threadIdx.x][i]);
    }
}

// ---------------- fp16 GEMM (validated R7): C = A @ Bt^T (+bias), 128x128 tile ----------------
#define GAST (128*40)
#define GBST (128*40)
#define GEMM_SMEM ((4*(GAST+GBST))*2)

template <typename TOUT>
__global__ void __launch_bounds__(256, 2) gemm16(
    const __half* __restrict__ A, int lda,
    const __half* __restrict__ Bt,
    TOUT* __restrict__ C, int ldc,
    const float* __restrict__ bias,
    int M, int N, int K)
{
    extern __shared__ __half sm[];
    __half* As = sm;
    __half* Bs = sm + 4*GAST;

    const int tid = threadIdx.x;
    const int bm = blockIdx.y * 128, bn = blockIdx.x * 128;
    const int wid = tid >> 5, lane = tid & 31;
    const int wr = (wid & 1) * 64, wc = (wid >> 1) * 32;
    const int r = lane >> 2, cl = lane & 3;

    float acc[4][4][4];
    #pragma unroll
    for (int i = 0; i < 4; ++i)
        #pragma unroll
        for (int j = 0; j < 4; ++j)
            #pragma unroll
            for (int k = 0; k < 4; ++k) acc[i][j][k] = 0.f;

    auto loadG = [&](int s, int kt) {
        #pragma unroll
        for (int i = 0; i < 2; ++i) {
            int idx = tid + i * 256;
            int row = idx >> 2, cc = idx & 3;
            cpa16(As + s*GAST + row*40 + cc*8,
                  A + (size_t)(bm + row) * lda + kt*32 + cc*8);
            cpa16(Bs + s*GBST + row*40 + cc*8,
                  Bt + (size_t)(bn + row) * K + kt*32 + cc*8);
        }
    };

    const int ktiles = K >> 5;
    #pragma unroll
    for (int s = 0; s < 3; ++s) { if (s < ktiles) loadG(s, s); CPA_COMMIT(); }

    const int a_row = (lane & 15);
    const int a_col = (lane >> 4) << 3;
    const int b_row = (lane & 7) + ((lane >> 4) << 3);
    const int b_col = (lane & 8);

    for (int kt = 0; kt < ktiles; ++kt) {
        cpa_wait<2>();
        __syncthreads();
        if (kt + 3 < ktiles) loadG((kt + 3) & 3, kt + 3);
        CPA_COMMIT();

        const __half* sA = As + (kt & 3) * GAST;
        const __half* sB = Bs + (kt & 3) * GBST;
        #pragma unroll
        for (int ks = 0; ks < 2; ++ks) {
            const int k0 = ks * 16;
            unsigned af[4][4], bf01[4], bf23[4];
            #pragma unroll
            for (int mt = 0; mt < 4; ++mt)
                ldsm_x4(af[mt], sA + (wr + mt*16 + a_row)*40 + k0 + a_col);
            ldsm_x4(bf01, sB + (wc      + b_row)*40 + k0 + b_col);
            ldsm_x4(bf23, sB + (wc + 16 + b_row)*40 + k0 + b_col);
            #pragma unroll
            for (int mt = 0; mt < 4; ++mt) {
                mma16(acc[mt][0], af[mt], bf01 + 0);
                mma16(acc[mt][1], af[mt], bf01 + 2);
                mma16(acc[mt][2], af[mt], bf23 + 0);
                mma16(acc[mt][3], af[mt], bf23 + 2);
            }
        }
    }

    #pragma unroll
    for (int mt = 0; mt < 4; ++mt)
        #pragma unroll
        for (int nt = 0; nt < 4; ++nt) {
            const int row = bm + wr + mt*16 + r;
            const int col = bn + wc + nt*8 + 2*cl;
            const float b0 = bias ? bias[col]     : 0.f;
            const float b1 = bias ? bias[col + 1] : 0.f;
            cstore2(C, (size_t)row * ldc + col,       acc[mt][nt][0] + b0, acc[mt][nt][1] + b1);
            cstore2(C, (size_t)(row + 8) * ldc + col, acc[mt][nt][2] + b0, acc[mt][nt][3] + b1);
        }
}

// ---------------- persistent LSTM layer kernel (2-D decomposition, fp16 X) ----------------
// 128 CTAs = 64 N-groups x 2 M-groups. CTA (bn = bx&63, bm = bx>>6) computes
// batch rows [bm*64, +64) x hidden cols [bn*16, +16) x 4 gates:
// GEMM M=64, N=64, K=1024. W slice (128KB) resident in smem.
// K-chunk 256 halfs: 4 pipeline rounds/step, 2-buffer ring (distance-1 prefetch,
// load issued AFTER the round barrier so the overwritten buffer is quiescent).
// 8 warps = 4 M-tiles x 2 N-halves; per-group counter sync (64 arrivals).
#define BST2 (64*1032)
#define AST4 (64*264)
#define XS_OFF3 ((BST2 + 2*AST4)*2)           // byte offset of X stage (fp16 [64][80])
#define LSTM_SMEM3 (XS_OFF3 + 64*80*2)        // 209920 B

__global__ void __launch_bounds__(256, 1) lstm_layer(
    const __half* __restrict__ WhT,    // [4096][1024]
    const __half* __restrict__ X,      // [T*128][4096] fp16
    __half* __restrict__ H,            // [T*128][1024]
    int* __restrict__ ctr)             // 2 ints (one per bm-group)
{
    extern __shared__ __half sm[];
    __half* Bs = sm;                   // 64 x 1032 (n = half*32 + gate*8 + j)
    __half* As = sm + BST2;            // 2 stages x 64 x 264
    __half* Xsh = (__half*)((char*)sm + XS_OFF3);   // 64 x 80 fp16

    const int tid = threadIdx.x, lane = tid & 31, wid = tid >> 5;
    const int r = lane >> 2, cl = lane & 3;
    const int bx = blockIdx.x;
    const int bn = bx & 63, bm = bx >> 6;
    const int mw = wid >> 1, wn = wid & 1;
    const int wr = mw * 16;
    const int jj = 2 * cl;
    const int gcol = bn * 16 + wn * 8 + jj;
    int* myctr = ctr + bm;

    // load W slice once: n = half*32 + gate*8 + j <- WhT row gate*1024 + bn*16 + half*8 + j
    #pragma unroll
    for (int i = 0; i < 32; ++i) {
        int idx = tid + i * 256;            // 0..8191 (16B units)
        int n = idx >> 7, cu = idx & 127;
        int half = n >> 5, gate = (n >> 3) & 3, j = n & 7;
        cpa16(Bs + n*1032 + cu*8,
              WhT + (size_t)(gate*1024 + bn*16 + half*8 + j) * 1024 + cu*8);
    }
    CPA_COMMIT();
    cpa_wait<0>();
    __syncthreads();

    float c0 = 0.f, c1 = 0.f, c2 = 0.f, c3 = 0.f;

    // A chunk: 64 rows (global bm*64+row) x 256 halfs of k (32KB), stride 264
    auto loadA = [&](__half* dst, const __half* hsrc, int ch) {
        #pragma unroll
        for (int i = 0; i < 8; ++i) {
            int idx = tid + i * 256;        // 0..2047 (16B units)
            int row = idx >> 5, cu = idx & 31;
            cpa16(dst + row*264 + cu*8,
                  hsrc + (size_t)(bm*64 + row)*1024 + ch*256 + cu*8);
        }
    };
    // stage X gate block [64 rows][4 gates x 16 cols] fp16 -> Xsh[row][gate*16 + c]
    auto loadX = [&](const __half* Xt) {
        #pragma unroll
        for (int i = 0; i < 2; ++i) {
            int u = tid + i * 256;          // 0..511 (16B granules)
            int rr = u >> 3, seg = u & 7;   // seg = gate*2 + q
            int g = seg >> 1, q = seg & 1;
            cpa16(Xsh + rr*80 + g*16 + q*8,
                  Xt + (size_t)(bm*64 + rr)*4096 + g*1024 + bn*16 + q*8);
        }
    };

    for (int t = 0; t < TT; ++t) {
        float acc[4][4];
        #pragma unroll
        for (int i = 0; i < 4; ++i)
            #pragma unroll
            for (int j = 0; j < 4; ++j) acc[i][j] = 0.f;

        const __half* Xt = X + (size_t)t * (BB * G4);

        if (t > 0) {
            const __half* hsrc = H + (size_t)(t - 1) * BB * NH;
            loadA(As + 0*AST4, hsrc, 0); loadX(Xt); CPA_COMMIT();

            #pragma unroll 1
            for (int kt = 0; kt < 4; ++kt) {
                cpa_wait<0>();      // chunk kt (issued last round / prologue) landed
                __syncthreads();    // everyone done reading the buffer we overwrite
                if (kt + 1 < 4) loadA(As + ((kt + 1) & 1) * AST4, hsrc, kt + 1);
                CPA_COMMIT();

                const __half* sA = As + (kt & 1) * AST4;
                #pragma unroll
                for (int ks = 0; ks < 16; ++ks) {
                    const int k0 = ks * 16;
                    unsigned af[4];
                    af[0] = *(const unsigned*)&sA[(wr + r    )*264 + k0 + jj];
                    af[1] = *(const unsigned*)&sA[(wr + r + 8)*264 + k0 + jj];
                    af[2] = *(const unsigned*)&sA[(wr + r    )*264 + k0 + jj + 8];
                    af[3] = *(const unsigned*)&sA[(wr + r + 8)*264 + k0 + jj + 8];
                    #pragma unroll
                    for (int nt = 0; nt < 4; ++nt) {
                        const __half* bp = Bs + (size_t)(wn*32 + nt*8 + r)*1032
                                              + kt*256 + k0 + jj;
                        unsigned bf[2];
                        bf[0] = *(const unsigned*)bp;
                        bf[1] = *(const unsigned*)(bp + 8);
                        mma16(acc[nt], af, bf);
                    }
                }
            }
        } else {
            loadX(Xt); CPA_COMMIT();
            cpa_wait<0>();
            __syncthreads();   // publish Xsh before epilogue reads
        }

        // gates + state update, all in registers (X from fp16 smem stage)
        const int rl0 = wr + r, rl1 = rl0 + 8;
        const int grow0 = bm*64 + rl0, grow1 = bm*64 + rl1;
        {
            const __half* xa = Xsh + rl0*80 + wn*8 + jj;
            float2 xf = __half22float2(*(const __half2*)(xa));
            float2 xi = __half22float2(*(const __half2*)(xa + 16));
            float2 xo = __half22float2(*(const __half2*)(xa + 32));
            float2 xg = __half22float2(*(const __half2*)(xa + 48));
            float f  = sigf(acc[0][0] + xf.x), ig  = sigf(acc[1][0] + xi.x);
            float o  = sigf(acc[2][0] + xo.x), gg  = tanhf(acc[3][0] + xg.x);
            c0 = f * c0 + ig * gg;
            float f1 = sigf(acc[0][1] + xf.y), ig1 = sigf(acc[1][1] + xi.y);
            float o1 = sigf(acc[2][1] + xo.y), gg1 = tanhf(acc[3][1] + xg.y);
            c1 = f1 * c1 + ig1 * gg1;
            __half2 hv = __floats2half2_rn(o * tanhf(c0), o1 * tanhf(c1));
            *(__half2*)&H[(size_t)t*BB*NH + (size_t)grow0*1024 + gcol] = hv;
        }
        {
            const __half* xb = Xsh + rl1*80 + wn*8 + jj;
            float2 xf = __half22float2(*(const __half2*)(xb));
            float2 xi = __half22float2(*(const __half2*)(xb + 16));
            float2 xo = __half22float2(*(const __half2*)(xb + 32));
            float2 xg = __half22float2(*(const __half2*)(xb + 48));
            float f  = sigf(acc[0][2] + xf.x), ig  = sigf(acc[1][2] + xi.x);
            float o  = sigf(acc[2][2] + xo.x), gg  = tanhf(acc[3][2] + xg.x);
            c2 = f * c2 + ig * gg;
            float f1 = sigf(acc[0][3] + xf.y), ig1 = sigf(acc[1][3] + xi.y);
            float o1 = sigf(acc[2][3] + xo.y), gg1 = tanhf(acc[3][3] + xg.y);
            c3 = f1 * c3 + ig1 * gg1;
            __half2 hv = __floats2half2_rn(o * tanhf(c2), o1 * tanhf(c3));
            *(__half2*)&H[(size_t)t*BB*NH + (size_t)grow1*1024 + gcol] = hv;
        }

        if (t + 1 < TT) {
            __syncthreads();       // all CTA threads' H stores happen-before tid0's release
            if (tid == 0) {
                asm volatile("red.release.gpu.global.add.u32 [%0], %1;"
                             :: "l"(myctr), "r"(1) : "memory");
                const int target = 64 * (t + 1);
                int v;
                while (true) {
                    asm volatile("ld.acquire.gpu.b32 %0, [%1];" : "=r"(v) : "l"(myctr));
                    if (v >= target) break;
                    __nanosleep(64);   // backoff
                }
            }
            __syncthreads();       // broadcast acquire to whole CTA
        }
    }
}

// ---------------- launch ----------------
extern "C" void kernel_launch(void* const* d_in, const int* in_sizes, int n_in,
                              void* d_out, int out_size) {
    (void)in_sizes; (void)n_in; (void)out_size;
    const float* inputs = (const float*)d_in[0];
    const float* emb    = (const float*)d_in[1];
    const float* w0     = (const float*)d_in[2];
    const float* b0     = (const float*)d_in[3];
    const float* w1     = (const float*)d_in[4];
    const float* b1     = (const float*)d_in[5];
    const float* outw   = (const float*)d_in[6];
    const float* outb   = (const float*)d_in[7];
    float* out = (float*)d_out;

    __half *inph, *embs, *H0, *H1, *embT, *w0xT, *w0hT, *w1xT, *w1hT, *owT, *X;
    int *ctr;
    cudaGetSymbolAddress((void**)&inph, g_inph);
    cudaGetSymbolAddress((void**)&embs, g_embs);
    cudaGetSymbolAddress((void**)&X,    g_X);
    cudaGetSymbolAddress((void**)&H0,   g_H0);
    cudaGetSymbolAddress((void**)&H1,   g_H1);
    cudaGetSymbolAddress((void**)&embT, g_embT);
    cudaGetSymbolAddress((void**)&w0xT, g_w0xT);
    cudaGetSymbolAddress((void**)&w0hT, g_w0hT);
    cudaGetSymbolAddress((void**)&w1xT, g_w1xT);
    cudaGetSymbolAddress((void**)&w1hT, g_w1hT);
    cudaGetSymbolAddress((void**)&owT,  g_owT);
    cudaGetSymbolAddress((void**)&ctr,  g_ctr);

    cudaFuncSetAttribute(lstm_layer,     cudaFuncAttributeMaxDynamicSharedMemorySize, LSTM_SMEM3);
    cudaFuncSetAttribute(gemm16<float>,  cudaFuncAttributeMaxDynamicSharedMemorySize, GEMM_SMEM);
    cudaFuncSetAttribute(gemm16<__half>, cudaFuncAttributeMaxDynamicSharedMemorySize, GEMM_SMEM);

    // prep
    f2h_kernel<<<1024, 256>>>(inputs, inph, TB * VV);
    {
        dim3 blk(32, 8);
        transpose_cvt<<<dim3(VV/32, EE/32), blk>>>(emb,                EE, embT, VV, EE);
        transpose_cvt<<<dim3(EE/32, G4/32), blk>>>(w0,                 G4, w0xT, EE, G4);
        transpose_cvt<<<dim3(NH/32, G4/32), blk>>>(w0 + (size_t)EE*G4, G4, w0hT, NH, G4);
        transpose_cvt<<<dim3(NH/32, G4/32), blk>>>(w1,                 G4, w1xT, NH, G4);
        transpose_cvt<<<dim3(NH/32, G4/32), blk>>>(w1 + (size_t)NH*G4, G4, w1hT, NH, G4);
        transpose_cvt<<<dim3(NH/32, VV/32), blk>>>(outw,               VV, owT,  NH, VV);
    }
    zero_i<<<1, 32>>>(ctr);

    // embs = inputs @ emb
    gemm16<__half><<<dim3(EE/128, TB/128), 256, GEMM_SMEM>>>(inph, VV, embT, embs, EE, nullptr, TB, EE, VV);
    // X = embs @ W0x + b0   (fp16 store)
    gemm16<__half><<<dim3(G4/128, TB/128), 256, GEMM_SMEM>>>(embs, EE, w0xT, X, G4, b0, TB, G4, EE);
    // layer 0 (persistent, 2-D split)
    lstm_layer<<<128, 256, LSTM_SMEM3>>>(w0hT, X, H0, ctr);
    // X = H0 @ W1x + b1   (fp16 store)
    gemm16<__half><<<dim3(G4/128, TB/128), 256, GEMM_SMEM>>>(H0, NH, w1xT, X, G4, b1, TB, G4, NH);
    // layer 1 (persistent, 2-D split)
    lstm_layer<<<128, 256, LSTM_SMEM3>>>(w1hT, X, H1, ctr + 2);
    // logits = H1 @ out_w + out_b
    gemm16<float><<<dim3(VV/128, TB/128), 256, GEMM_SMEM>>>(H1, NH, owT, out, VV, outb, TB, VV, NH);
}